// round 1
// baseline (speedup 1.0000x reference)
#include <cuda_runtime.h>
#include <cuda_bf16.h>

// WeldonPool2d: per row of N=1024 floats, out = (mean(top10) + mean(bottom10)) / 2.
// One warp per row. Each lane holds 32 register-resident values (8x float4,
// coalesced), bitonic-sorts them branch-free, then the warp extracts the global
// top-10 / bottom-10 via shfl reductions + owner-shift merge.

#define WARPS_PER_BLOCK 8
#define THREADS (WARPS_PER_BLOCK * 32)
#define ROW_N 1024

__global__ void __launch_bounds__(THREADS)
weldon_kernel(const float* __restrict__ x, float* __restrict__ out, int rows) {
    const int warp = blockIdx.x * WARPS_PER_BLOCK + (threadIdx.x >> 5);
    const int lane = threadIdx.x & 31;
    if (warp >= rows) return;

    // ---- Load 32 elements per lane as 8 coalesced float4 ----
    const float4* p = reinterpret_cast<const float4*>(x) + (size_t)warp * (ROW_N / 4);
    float v[32];
#pragma unroll
    for (int i = 0; i < 8; i++) {
        float4 q = __ldg(&p[lane + 32 * i]);
        v[4 * i + 0] = q.x;
        v[4 * i + 1] = q.y;
        v[4 * i + 2] = q.z;
        v[4 * i + 3] = q.w;
    }

    // ---- Branch-free bitonic sort (ascending) of 32 register values ----
    // All indices are compile-time constants after unrolling -> stays in registers.
#pragma unroll
    for (int k = 2; k <= 32; k <<= 1) {
#pragma unroll
        for (int j = k >> 1; j > 0; j >>= 1) {
#pragma unroll
            for (int i = 0; i < 32; i++) {
                int l = i ^ j;
                if (l > i) {
                    bool up = ((i & k) == 0);
                    float a = v[i], b = v[l];
                    float mn = fminf(a, b);
                    float mx = fmaxf(a, b);
                    v[i] = up ? mn : mx;
                    v[l] = up ? mx : mn;
                }
            }
        }
    }

    // ---- Per-lane candidate windows ----
    // t[0..9]: lane's top-10, descending (t[0] = lane max)
    // b[0..9]: lane's bottom-10, ascending (b[0] = lane min)
    float t[10], b[10];
#pragma unroll
    for (int i = 0; i < 10; i++) {
        t[i] = v[31 - i];
        b[i] = v[i];
    }

    float sumT = 0.0f, sumB = 0.0f;

    // ---- 10 extraction rounds: global max / min of the 32 list heads ----
#pragma unroll
    for (int r = 0; r < 10; r++) {
        // global max of heads
        float m = t[0];
#pragma unroll
        for (int off = 16; off > 0; off >>= 1)
            m = fmaxf(m, __shfl_xor_sync(0xffffffffu, m, off));
        sumT += m;
        unsigned msk = __ballot_sync(0xffffffffu, t[0] == m);
        int owner = __ffs(msk) - 1;
        if (lane == owner) {
#pragma unroll
            for (int i = 0; i < 9; i++) t[i] = t[i + 1];
        }

        // global min of heads
        float mm = b[0];
#pragma unroll
        for (int off = 16; off > 0; off >>= 1)
            mm = fminf(mm, __shfl_xor_sync(0xffffffffu, mm, off));
        sumB += mm;
        unsigned msk2 = __ballot_sync(0xffffffffu, b[0] == mm);
        int owner2 = __ffs(msk2) - 1;
        if (lane == owner2) {
#pragma unroll
            for (int i = 0; i < 9; i++) b[i] = b[i + 1];
        }
    }

    // out = (sumT/10 + sumB/10) / 2 = (sumT + sumB) * 0.05
    if (lane == 0) out[warp] = (sumT + sumB) * 0.05f;
}

extern "C" void kernel_launch(void* const* d_in, const int* in_sizes, int n_in,
                              void* d_out, int out_size) {
    const float* x = (const float*)d_in[0];
    float* out = (float*)d_out;
    const int rows = in_sizes[0] / ROW_N;  // 65536
    const int blocks = (rows + WARPS_PER_BLOCK - 1) / WARPS_PER_BLOCK;
    weldon_kernel<<<blocks, THREADS>>>(x, out, rows);
}

// round 4
// speedup vs baseline: 1.0545x; 1.0545x over previous
#include <cuda_runtime.h>
#include <cuda_bf16.h>

// WeldonPool2d: per row of N=1024 floats, out = (mean(top10) + mean(bottom10)) / 2.
//
// R4 (exact fp32 only — sm_103a has no packed f32 min/max and no redux.f32):
//  - one warp per row, 32 values/lane, register bitonic sort (FMNMX).
//  - final merge stage pruned: only outputs {0..9, 22..31} need to be exact,
//    so the j=2 layer drops 4 CEs and the j=1 layer drops 6 CEs.
//  - each lane's sorted top-10/bottom-10 spilled to smem once; the 10-round
//    warp extraction pops via cursor+LDS+SEL instead of register-window
//    shifts (removes ~180 ALU SELs/row; LDS/STS ride the idle MIO pipe).

#define WARPS_PER_BLOCK 8
#define THREADS (WARPS_PER_BLOCK * 32)
#define ROW_N 1024
#define WIN_STRIDE 21   // 20 floats per lane + 1 pad (conflict-free STS)

__global__ void __launch_bounds__(THREADS)
weldon_kernel(const float* __restrict__ x, float* __restrict__ out, int rows) {
    __shared__ float win[WARPS_PER_BLOCK][32 * WIN_STRIDE];

    const int wib  = threadIdx.x >> 5;
    const int warp = blockIdx.x * WARPS_PER_BLOCK + wib;
    const int lane = threadIdx.x & 31;
    if (warp >= rows) return;

    // ---- Load 32 elements per lane as 8 coalesced float4 ----
    const float4* p = reinterpret_cast<const float4*>(x) + (size_t)warp * (ROW_N / 4);
    float v[32];
#pragma unroll
    for (int i = 0; i < 8; i++) {
        float4 q = __ldg(&p[lane + 32 * i]);
        v[4 * i + 0] = q.x;
        v[4 * i + 1] = q.y;
        v[4 * i + 2] = q.z;
        v[4 * i + 3] = q.w;
    }

    // ---- Branch-free bitonic sort (ascending) of 32 register values ----
    // Final merge (k=32) pruned: outputs 10..21 are never consumed, so
    //   j==2 layer: skip pairs (12,14),(13,15),(16,18),(17,19)
    //   j==1 layer: skip pairs (10,11),(12,13),(14,15),(16,17),(18,19),(20,21)
#pragma unroll
    for (int k = 2; k <= 32; k <<= 1) {
#pragma unroll
        for (int j = k >> 1; j > 0; j >>= 1) {
#pragma unroll
            for (int i = 0; i < 32; i++) {
                int l = i ^ j;
                if (l > i) {
                    if (k == 32 && j == 2 && (i >= 12 && i <= 17)) continue;
                    if (k == 32 && j == 1 && (i >= 10 && i <= 20)) continue;
                    bool up = ((i & k) == 0);
                    float a = v[i], b = v[l];
                    float mn = fminf(a, b);
                    float mx = fmaxf(a, b);
                    v[i] = up ? mn : mx;
                    v[l] = up ? mx : mn;
                }
            }
        }
    }

    // ---- Spill per-lane windows to smem (each lane reads only its own) ----
    // w[0..9]  = top-10 descending (w[0] = lane max)
    // w[10..19]= bottom-10 ascending (w[10] = lane min)
    float* w = &win[wib][lane * WIN_STRIDE];
#pragma unroll
    for (int i = 0; i < 10; i++) {
        w[i]      = v[31 - i];
        w[10 + i] = v[i];
    }

    // ---- 10 extraction rounds; heads in registers, pops via cursor+LDS ----
    float ht = v[31];   // current top head
    float hb = v[0];    // current bottom head
    int ct = 0;         // top cursor   (offset into w[0..9])
    int cb = 10;        // bottom cursor(offset into w[10..19])
    float sT = 0.0f, sB = 0.0f;

#pragma unroll
    for (int r = 0; r < 10; r++) {
        // global max of top heads
        float m = ht;
#pragma unroll
        for (int off = 16; off > 0; off >>= 1)
            m = fmaxf(m, __shfl_xor_sync(0xffffffffu, m, off));
        sT += m;
        unsigned mk = __ballot_sync(0xffffffffu, ht == m);
        int own = (lane == __ffs(mk) - 1);
        if (r < 9) {
            ct += own;
            float nt = w[ct];          // unconditional LDS, in-bounds (ct<=9)
            ht = own ? nt : ht;
        }

        // global min of bottom heads
        float mm = hb;
#pragma unroll
        for (int off = 16; off > 0; off >>= 1)
            mm = fminf(mm, __shfl_xor_sync(0xffffffffu, mm, off));
        sB += mm;
        unsigned mk2 = __ballot_sync(0xffffffffu, hb == mm);
        int own2 = (lane == __ffs(mk2) - 1);
        if (r < 9) {
            cb += own2;
            float nb = w[cb];          // in-bounds (cb<=19)
            hb = own2 ? nb : hb;
        }
    }

    if (lane == 0) out[warp] = (sT + sB) * 0.05f;
}

extern "C" void kernel_launch(void* const* d_in, const int* in_sizes, int n_in,
                              void* d_out, int out_size) {
    const float* x = (const float*)d_in[0];
    float* out = (float*)d_out;
    const int rows = in_sizes[0] / ROW_N;  // 65536
    const int blocks = (rows + WARPS_PER_BLOCK - 1) / WARPS_PER_BLOCK;
    weldon_kernel<<<blocks, THREADS>>>(x, out, rows);
}